// round 6
// baseline (speedup 1.0000x reference)
#include <cuda_runtime.h>
#include <cuda_fp16.h>
#include <stdint.h>
#include <math.h>

#define TT 2048     // tokens
#define HH 2048     // hidden
#define FF 1408     // moe intermediate
#define EE 60       // experts
#define TK 4        // top-k
#define SS 5632     // shared intermediate
#define NP (TT*TK)  // routed pairs

// ---- scratch ----
__device__ float g_ybuf[(size_t)TT*SS];
__device__ float g_hbuf[(size_t)NP*FF];
__device__ float g_pbuf[(size_t)NP*HH];
__device__ float g_topw[NP];
__device__ int   g_topidx[NP];
__device__ float g_sig[TT];
__device__ int   g_off[EE+1];
__device__ int   g_tok[NP];
__device__ int   g_pos[NP];
// MoE tile lists: full 128-row tiles + 32-row tail tiles
__device__ int   g_ftE[64],  g_ftM[64],  g_nft;
__device__ int   g_ttE[240], g_ttM[240], g_ntt;

// ============================ helpers ============================
__device__ __forceinline__ uint32_t smem_u32(const void* p) {
    uint32_t a;
    asm("{ .reg .u64 t; cvta.to.shared.u64 t, %1; cvt.u32.u64 %0, t; }" : "=r"(a) : "l"(p));
    return a;
}
__device__ __forceinline__ void ldsm4(uint32_t r[4], uint32_t addr) {
    asm volatile("ldmatrix.sync.aligned.m8n8.x4.shared.b16 {%0,%1,%2,%3}, [%4];"
        : "=r"(r[0]), "=r"(r[1]), "=r"(r[2]), "=r"(r[3]) : "r"(addr));
}
__device__ __forceinline__ void ldsm4t(uint32_t r[4], uint32_t addr) {
    asm volatile("ldmatrix.sync.aligned.m8n8.x4.trans.shared.b16 {%0,%1,%2,%3}, [%4];"
        : "=r"(r[0]), "=r"(r[1]), "=r"(r[2]), "=r"(r[3]) : "r"(addr));
}
__device__ __forceinline__ void mma_f16(float c[4], const uint32_t a[4], uint32_t b0, uint32_t b1) {
    asm volatile(
        "mma.sync.aligned.m16n8k16.row.col.f32.f16.f16.f32 "
        "{%0,%1,%2,%3}, {%4,%5,%6,%7}, {%8,%9}, {%0,%1,%2,%3};\n"
        : "+f"(c[0]), "+f"(c[1]), "+f"(c[2]), "+f"(c[3])
        : "r"(a[0]), "r"(a[1]), "r"(a[2]), "r"(a[3]), "r"(b0), "r"(b1));
}
__device__ __forceinline__ uint32_t pack_h2(__half a, __half b) {
    __half2 h = __halves2half2(a, b);
    return *(uint32_t*)&h;
}
__device__ __forceinline__ float silu_f(float g) { return g / (1.f + __expf(-g)); }

// ============================ router ============================
__global__ void router_kernel(const float* __restrict__ x,
                              const float* __restrict__ rw,
                              const float* __restrict__ seg)
{
    int t = blockIdx.x;
    int tid = threadIdx.x;              // 64 threads
    __shared__ float xs[HH];
    __shared__ float lg[EE];
    __shared__ float red[64];
    const float* xr = x + (size_t)t*HH;
    for (int i = tid; i < HH; i += 64) xs[i] = xr[i];
    __syncthreads();
    if (tid < EE) {
        float a=0.f,b=0.f,c=0.f,d=0.f;
        for (int k = 0; k < HH; k += 4) {
            a = fmaf(xs[k+0], rw[(size_t)(k+0)*EE + tid], a);
            b = fmaf(xs[k+1], rw[(size_t)(k+1)*EE + tid], b);
            c = fmaf(xs[k+2], rw[(size_t)(k+2)*EE + tid], c);
            d = fmaf(xs[k+3], rw[(size_t)(k+3)*EE + tid], d);
        }
        lg[tid] = (a+b)+(c+d);
    }
    float p = 0.f;
    for (int k = tid; k < HH; k += 64) p = fmaf(xs[k], seg[k], p);
    red[tid] = p;
    __syncthreads();
    if (tid == 0) {
        float m = lg[0];
        for (int e = 1; e < EE; e++) m = fmaxf(m, lg[e]);
        float s = 0.f;
        for (int e = 0; e < EE; e++) { float v = __expf(lg[e]-m); lg[e] = v; s += v; }
        float inv = 1.f/s;
        for (int e = 0; e < EE; e++) lg[e] *= inv;
        for (int j = 0; j < TK; j++) {
            int bi = 0; float bv = lg[0];
            for (int e = 1; e < EE; e++) { if (lg[e] > bv) { bv = lg[e]; bi = e; } }
            g_topidx[t*TK+j] = bi;
            g_topw[t*TK+j]  = bv;
            lg[bi] = -1.f;
        }
        float ss = 0.f;
        for (int i = 0; i < 64; i++) ss += red[i];
        g_sig[t] = 1.f/(1.f + __expf(-ss));
    }
}

__global__ void build1_kernel()
{
    __shared__ int cnt[EE];
    int tid = threadIdx.x;              // 256
    if (tid < EE) cnt[tid] = 0;
    __syncthreads();
    for (int p = tid; p < NP; p += 256) atomicAdd(&cnt[g_topidx[p]], 1);
    __syncthreads();
    if (tid == 0) {
        int s = 0;
        for (int e = 0; e < EE; e++) { g_off[e] = s; s += cnt[e]; }
        g_off[EE] = s;
        // build tile lists: full 128-row tiles + 32-row tails
        int nf = 0, nt = 0;
        for (int e = 0; e < EE; e++) {
            int c = cnt[e];
            int f = c >> 7;
            for (int i = 0; i < f; i++) { g_ftE[nf] = e; g_ftM[nf] = i*128; nf++; }
            int rem = c - f*128;
            int t2 = (rem + 31) >> 5;
            for (int i = 0; i < t2; i++) { g_ttE[nt] = e; g_ttM[nt] = f*128 + i*32; nt++; }
        }
        g_nft = nf;
        g_ntt = nt;
    }
}

__global__ void build2_kernel()
{
    __shared__ int sidx[NP];            // 32 KB
    int tid = threadIdx.x;              // 256, grid 32
    for (int i = tid; i < NP; i += 256) sidx[i] = g_topidx[i];
    __syncthreads();
    int p = blockIdx.x*256 + tid;
    int e = sidx[p];
    int r = 0;
    for (int q = 0; q < p; q++) r += (sidx[q] == e);
    int pos = g_off[e] + r;
    g_tok[pos] = p >> 2;
    g_pos[p]   = pos;
}

// ============================ generic fill ============================
// Stage layout (TM rows): Ahi [TM][40]h | Alo [TM][40]h | B [32][136]h
// A filled by first 2*TM threads (2 per row, 16 floats each); B by all 256.
template<int TM>
__device__ __forceinline__ void fill_slab(char* base,
                                          const float* __restrict__ aptr,
                                          const float* __restrict__ bptr,
                                          int s, int N_, int tid)
{
    constexpr int ALO_ = TM*80;
    constexpr int BOF_ = 2*TM*80;
    if (TM == 128 || tid < 2*TM) {
        const int ar = tid >> 1, ah = (tid & 1)*16;
        const float* ap = aptr + s*32;
        uint32_t wh[8], wl[8];
        #pragma unroll
        for (int i = 0; i < 4; i++) {
            float4 a = *(const float4*)(ap + i*4);
            __half h0 = __float2half_rn(a.x), h1 = __float2half_rn(a.y);
            __half h2 = __float2half_rn(a.z), h3 = __float2half_rn(a.w);
            wh[2*i]   = pack_h2(h0, h1);
            wh[2*i+1] = pack_h2(h2, h3);
            wl[2*i]   = pack_h2(__float2half_rn(a.x - __half2float(h0)),
                                __float2half_rn(a.y - __half2float(h1)));
            wl[2*i+1] = pack_h2(__float2half_rn(a.z - __half2float(h2)),
                                __float2half_rn(a.w - __half2float(h3)));
        }
        char* pa = base + ar*80 + ah*2;
        *(uint4*)(pa)      = make_uint4(wh[0], wh[1], wh[2], wh[3]);
        *(uint4*)(pa + 16) = make_uint4(wh[4], wh[5], wh[6], wh[7]);
        char* pl = base + ALO_ + ar*80 + ah*2;
        *(uint4*)(pl)      = make_uint4(wl[0], wl[1], wl[2], wl[3]);
        *(uint4*)(pl + 16) = make_uint4(wl[4], wl[5], wl[6], wl[7]);
    }
    {
        const int bk = tid >> 3, bn = (tid & 7)*16;
        const float* bp = bptr + (size_t)s*32*N_;
        uint32_t wb[8];
        #pragma unroll
        for (int i = 0; i < 4; i++) {
            float4 b = *(const float4*)(bp + i*4);
            wb[2*i]   = pack_h2(__float2half_rn(b.x), __float2half_rn(b.y));
            wb[2*i+1] = pack_h2(__float2half_rn(b.z), __float2half_rn(b.w));
        }
        char* pb = base + BOF_ + bk*272 + bn*2;
        *(uint4*)(pb)      = make_uint4(wb[0], wb[1], wb[2], wb[3]);
        *(uint4*)(pb + 16) = make_uint4(wb[4], wb[5], wb[6], wb[7]);
    }
}

// ============================ dense HMMA GEMM (shared expert) ============================
// CTA 128x128, BK=32, fp16x2 split on A, warp tile 32x64.
#define DSTG 29184
#define DSMEM (2*DSTG)

template<int MODE>
__global__ void __launch_bounds__(256,2) dense_hmma(const float* __restrict__ Aex,
                                                    const float* __restrict__ Bw,
                                                    float* __restrict__ Cex)
{
    constexpr int K = (MODE==2) ? SS : HH;
    constexpr int N = (MODE==2) ? HH : SS;
    constexpr int NSLAB = K/32;
    constexpr int ALO_ = 128*80, BOF_ = 2*128*80;

    extern __shared__ __align__(16) char dsm[];
    const uint32_t sb = smem_u32(dsm);

    const int tid = threadIdx.x, lane = tid & 31, w = tid >> 5;
    const int wm = (w & 3)*32, wn = (w >> 2)*64;
    const int mb = blockIdx.y*128;
    const int nb = blockIdx.x*128;
    const float* Abase = (MODE==2) ? (const float*)g_ybuf : Aex;

    const int ar = tid >> 1, ah = (tid & 1)*16;
    const float* aptr = Abase + (size_t)(mb + ar)*K + ah;
    const int bk = tid >> 3, bn = (tid & 7)*16;
    const float* bptr = Bw + (size_t)bk*N + nb + bn;

    const int lr = lane & 15, lc = lane >> 4;
    const uint32_t aoff0 = (uint32_t)(((wm + lr)*40 + lc*8)*2);
    const uint32_t aoff1 = aoff0 + 16*80;
    uint32_t boff[4];
    #pragma unroll
    for (int np = 0; np < 4; np++)
        boff[np] = (uint32_t)((lr*136 + wn + np*16 + lc*8)*2) + BOF_;

    float acc[2][8][4] = {};

    fill_slab<128>(dsm, aptr, bptr, 0, N, tid);
    __syncthreads();

    for (int s = 0; s < NSLAB; s++) {
        const uint32_t sbb = sb + (uint32_t)((s & 1)*DSTG);
        if (s + 1 < NSLAB)
            fill_slab<128>(dsm + ((s+1) & 1)*DSTG, aptr, bptr, s+1, N, tid);
        #pragma unroll
        for (int ks = 0; ks < 2; ks++) {
            const uint32_t kbA = ks*32;
            const uint32_t kbB = ks*16*272;
            uint32_t a0h[4], a1h[4], a0l[4], a1l[4];
            ldsm4(a0h, sbb + aoff0 + kbA);
            ldsm4(a1h, sbb + aoff1 + kbA);
            ldsm4(a0l, sbb + ALO_ + aoff0 + kbA);
            ldsm4(a1l, sbb + ALO_ + aoff1 + kbA);
            #pragma unroll
            for (int np = 0; np < 4; np++) {
                uint32_t bb[4];
                ldsm4t(bb, sbb + boff[np] + kbB);
                mma_f16(acc[0][np*2],   a0h, bb[0], bb[1]);
                mma_f16(acc[0][np*2],   a0l, bb[0], bb[1]);
                mma_f16(acc[0][np*2+1], a0h, bb[2], bb[3]);
                mma_f16(acc[0][np*2+1], a0l, bb[2], bb[3]);
                mma_f16(acc[1][np*2],   a1h, bb[0], bb[1]);
                mma_f16(acc[1][np*2],   a1l, bb[0], bb[1]);
                mma_f16(acc[1][np*2+1], a1h, bb[2], bb[3]);
                mma_f16(acc[1][np*2+1], a1l, bb[2], bb[3]);
            }
        }
        __syncthreads();
    }

    #pragma unroll
    for (int mt = 0; mt < 2; mt++) {
        const int r0 = mb + wm + mt*16 + (lane >> 2);
        const int r1 = r0 + 8;
        #pragma unroll
        for (int nt = 0; nt < 8; nt++) {
            const int col = nb + wn + nt*8 + (lane & 3)*2;
            const float* c = acc[mt][nt];
            if (MODE == 0) {
                *(float2*)&g_ybuf[(size_t)r0*SS + col] = make_float2(c[0], c[1]);
                *(float2*)&g_ybuf[(size_t)r1*SS + col] = make_float2(c[2], c[3]);
            } else if (MODE == 1) {
                float2 g0 = *(float2*)&g_ybuf[(size_t)r0*SS + col];
                float2 g1 = *(float2*)&g_ybuf[(size_t)r1*SS + col];
                *(float2*)&g_ybuf[(size_t)r0*SS + col] =
                    make_float2(silu_f(g0.x)*c[0], silu_f(g0.y)*c[1]);
                *(float2*)&g_ybuf[(size_t)r1*SS + col] =
                    make_float2(silu_f(g1.x)*c[2], silu_f(g1.y)*c[3]);
            } else {
                float s0 = g_sig[r0], s1 = g_sig[r1];
                *(float2*)&Cex[(size_t)r0*HH + col] = make_float2(s0*c[0], s0*c[1]);
                *(float2*)&Cex[(size_t)r1*HH + col] = make_float2(s1*c[2], s1*c[3]);
            }
        }
    }
}

// ============================ MoE HMMA GEMM (tile-list driven) ============================
// TM=128: warp grid 4x2 (warp 32x64). TM=32: warp grid 1x8 (warp 32x16).
template<int MODE, int TM>
__global__ void __launch_bounds__(256,2) moe_hmma(const float* __restrict__ X,
                                                  const float* __restrict__ W)
{
    constexpr int K = (MODE==2) ? FF : HH;
    constexpr int N = (MODE==2) ? HH : FF;
    constexpr int NSLAB = K/32;
    constexpr int NWM = TM/32;           // 4 or 1
    constexpr int WNC = 128/(8/NWM);     // 64 or 16
    constexpr int NPW = WNC/16;          // 4 or 1
    constexpr int ALO_ = TM*80, BOF_ = 2*TM*80;
    constexpr int STG_ = BOF_ + 8704;

    const int ti = blockIdx.y;
    const int ntile = (TM==128) ? g_nft : g_ntt;
    if (ti >= ntile) return;
    const int e  = (TM==128) ? g_ftE[ti] : g_ttE[ti];
    const int m0 = (TM==128) ? g_ftM[ti] : g_ttM[ti];
    const int base = g_off[e] + m0;
    int rows = g_off[e+1] - base;
    if (rows > TM) rows = TM;

    extern __shared__ __align__(16) char dsm[];
    const uint32_t sb = smem_u32(dsm);

    const int tid = threadIdx.x, lane = tid & 31, w = tid >> 5;
    const int wm = (w % NWM)*32, wn = (w / NWM)*WNC;
    const int nb = blockIdx.x*128;
    const float* Bp = W + (size_t)e*K*N;

    const int ar = tid >> 1, ah = (tid & 1)*16;
    const float* aptr;
    {
        int rc = (ar < rows) ? ar : (rows - 1);
        if (MODE < 2) aptr = X + (size_t)g_tok[base + rc]*HH + ah;
        else          aptr = g_hbuf + (size_t)(base + rc)*FF + ah;
    }
    const int bk = tid >> 3, bn = (tid & 7)*16;
    const float* bptr = Bp + (size_t)bk*N + nb + bn;

    const int lr = lane & 15, lc = lane >> 4;
    const uint32_t aoff0 = (uint32_t)(((wm + lr)*40 + lc*8)*2);
    const uint32_t aoff1 = aoff0 + 16*80;
    uint32_t boff[NPW];
    #pragma unroll
    for (int np = 0; np < NPW; np++)
        boff[np] = (uint32_t)((lr*136 + wn + np*16 + lc*8)*2) + BOF_;

    float acc[2][2*NPW][4] = {};

    fill_slab<TM>(dsm, aptr, bptr, 0, N, tid);
    __syncthreads();

    for (int s = 0; s < NSLAB; s++) {
        const uint32_t sbb = sb + (uint32_t)((s & 1)*STG_);
        if (s + 1 < NSLAB)
            fill_slab<TM>(dsm + ((s+1) & 1)*STG_, aptr, bptr, s+1, N, tid);
        #pragma unroll
        for (int ks = 0; ks < 2; ks++) {
            const uint32_t kbA = ks*32;
            const uint32_t kbB = ks*16*272;
            uint32_t a0h[4], a1h[4], a0l[4], a1l[4];
            ldsm4(a0h, sbb + aoff0 + kbA);
            ldsm4(a1h, sbb + aoff1 + kbA);
            ldsm4(a0l, sbb + ALO_ + aoff0 + kbA);
            ldsm4(a1l, sbb + ALO_ + aoff1 + kbA);
            #pragma unroll
            for (int np = 0; np < NPW; np++) {
                uint32_t bb[4];
                ldsm4t(bb, sbb + boff[np] + kbB);
                mma_f16(acc[0][np*2],   a0h, bb[0], bb[1]);
                mma_f16(acc[0][np*2],   a0l, bb[0], bb[1]);
                mma_f16(acc[0][np*2+1], a0h, bb[2], bb[3]);
                mma_f16(acc[0][np*2+1], a0l, bb[2], bb[3]);
                mma_f16(acc[1][np*2],   a1h, bb[0], bb[1]);
                mma_f16(acc[1][np*2],   a1l, bb[0], bb[1]);
                mma_f16(acc[1][np*2+1], a1h, bb[2], bb[3]);
                mma_f16(acc[1][np*2+1], a1l, bb[2], bb[3]);
            }
        }
        __syncthreads();
    }

    #pragma unroll
    for (int mt = 0; mt < 2; mt++) {
        const int rl0 = wm + mt*16 + (lane >> 2);
        const int rl1 = rl0 + 8;
        const bool v0 = rl0 < rows;
        const bool v1 = rl1 < rows;
        #pragma unroll
        for (int nt = 0; nt < 2*NPW; nt++) {
            const int col = nb + wn + nt*8 + (lane & 3)*2;
            const float* c = acc[mt][nt];
            if (MODE == 0) {
                if (v0) *(float2*)&g_hbuf[(size_t)(base+rl0)*FF + col] = make_float2(c[0], c[1]);
                if (v1) *(float2*)&g_hbuf[(size_t)(base+rl1)*FF + col] = make_float2(c[2], c[3]);
            } else if (MODE == 1) {
                if (v0) {
                    float2 g = *(float2*)&g_hbuf[(size_t)(base+rl0)*FF + col];
                    *(float2*)&g_hbuf[(size_t)(base+rl0)*FF + col] =
                        make_float2(silu_f(g.x)*c[0], silu_f(g.y)*c[1]);
                }
                if (v1) {
                    float2 g = *(float2*)&g_hbuf[(size_t)(base+rl1)*FF + col];
                    *(float2*)&g_hbuf[(size_t)(base+rl1)*FF + col] =
                        make_float2(silu_f(g.x)*c[2], silu_f(g.y)*c[3]);
                }
            } else {
                if (v0) *(float2*)&g_pbuf[(size_t)(base+rl0)*HH + col] = make_float2(c[0], c[1]);
                if (v1) *(float2*)&g_pbuf[(size_t)(base+rl1)*HH + col] = make_float2(c[2], c[3]);
            }
        }
    }
}

// ============================ combine ============================
__global__ void combine_kernel(float* __restrict__ out)
{
    int t = blockIdx.x, tid = threadIdx.x;
    int p0 = g_pos[t*4+0], p1 = g_pos[t*4+1], p2 = g_pos[t*4+2], p3 = g_pos[t*4+3];
    float w0 = g_topw[t*4+0], w1 = g_topw[t*4+1], w2 = g_topw[t*4+2], w3 = g_topw[t*4+3];
    const float* r0 = g_pbuf + (size_t)p0*HH;
    const float* r1 = g_pbuf + (size_t)p1*HH;
    const float* r2 = g_pbuf + (size_t)p2*HH;
    const float* r3 = g_pbuf + (size_t)p3*HH;
    for (int c = tid; c < HH; c += 256) {
        float v = out[(size_t)t*HH + c];
        v = fmaf(w0, r0[c], v);
        v = fmaf(w1, r1[c], v);
        v = fmaf(w2, r2[c], v);
        v = fmaf(w3, r3[c], v);
        out[(size_t)t*HH + c] = v;
    }
}

// ============================ launch ============================
#define MSTG128 (2*128*80 + 8704)
#define MSTG32  (2*32*80 + 8704)

extern "C" void kernel_launch(void* const* d_in, const int* in_sizes, int n_in,
                              void* d_out, int out_size)
{
    const float* x   = (const float*)d_in[0];
    const float* rw  = (const float*)d_in[1];
    const float* wg  = (const float*)d_in[2];
    const float* wu  = (const float*)d_in[3];
    const float* wd  = (const float*)d_in[4];
    const float* shg = (const float*)d_in[5];
    const float* shu = (const float*)d_in[6];
    const float* shd = (const float*)d_in[7];
    const float* seg = (const float*)d_in[8];
    float* out = (float*)d_out;
    (void)in_sizes; (void)n_in; (void)out_size;

    cudaFuncSetAttribute(dense_hmma<0>, cudaFuncAttributeMaxDynamicSharedMemorySize, DSMEM);
    cudaFuncSetAttribute(dense_hmma<1>, cudaFuncAttributeMaxDynamicSharedMemorySize, DSMEM);
    cudaFuncSetAttribute(dense_hmma<2>, cudaFuncAttributeMaxDynamicSharedMemorySize, DSMEM);
    cudaFuncSetAttribute(moe_hmma<0,128>, cudaFuncAttributeMaxDynamicSharedMemorySize, 2*MSTG128);
    cudaFuncSetAttribute(moe_hmma<1,128>, cudaFuncAttributeMaxDynamicSharedMemorySize, 2*MSTG128);
    cudaFuncSetAttribute(moe_hmma<2,128>, cudaFuncAttributeMaxDynamicSharedMemorySize, 2*MSTG128);
    cudaFuncSetAttribute(moe_hmma<0,32>,  cudaFuncAttributeMaxDynamicSharedMemorySize, 2*MSTG32);
    cudaFuncSetAttribute(moe_hmma<1,32>,  cudaFuncAttributeMaxDynamicSharedMemorySize, 2*MSTG32);
    cudaFuncSetAttribute(moe_hmma<2,32>,  cudaFuncAttributeMaxDynamicSharedMemorySize, 2*MSTG32);

    router_kernel<<<TT, 64>>>(x, rw, seg);
    build1_kernel<<<1, 256>>>();
    build2_kernel<<<32, 256>>>();

    // shared expert
    dense_hmma<0><<<dim3(SS/128, TT/128), 256, DSMEM>>>(x, shg, nullptr);
    dense_hmma<1><<<dim3(SS/128, TT/128), 256, DSMEM>>>(x, shu, nullptr);
    dense_hmma<2><<<dim3(HH/128, TT/128), 256, DSMEM>>>(nullptr, shd, out);

    // MoE experts: full tiles (TM=128) + tail tiles (TM=32)
    moe_hmma<0,128><<<dim3(FF/128, 64),  256, 2*MSTG128>>>(x, wg);
    moe_hmma<0,32> <<<dim3(FF/128, 240), 256, 2*MSTG32 >>>(x, wg);
    moe_hmma<1,128><<<dim3(FF/128, 64),  256, 2*MSTG128>>>(x, wu);
    moe_hmma<1,32> <<<dim3(FF/128, 240), 256, 2*MSTG32 >>>(x, wu);
    moe_hmma<2,128><<<dim3(HH/128, 64),  256, 2*MSTG128>>>(nullptr, wd);
    moe_hmma<2,32> <<<dim3(HH/128, 240), 256, 2*MSTG32 >>>(nullptr, wd);

    combine_kernel<<<TT, 256>>>(out);
}

// round 7
// speedup vs baseline: 1.0397x; 1.0397x over previous
#include <cuda_runtime.h>
#include <cuda_fp16.h>
#include <stdint.h>
#include <math.h>

#define TT 2048     // tokens
#define HH 2048     // hidden
#define FF 1408     // moe intermediate
#define EE 60       // experts
#define TK 4        // top-k
#define SS 5632     // shared intermediate
#define NP (TT*TK)  // routed pairs

// ---- scratch ----
__device__ float g_ybuf[(size_t)TT*SS];
__device__ float g_hbuf[(size_t)NP*FF];
__device__ float g_pbuf[(size_t)NP*HH];
__device__ float g_topw[NP];
__device__ int   g_topidx[NP];
__device__ float g_sig[TT];
__device__ int   g_off[EE+1];
__device__ int   g_tok[NP];
__device__ int   g_pos[NP];

// ============================ helpers ============================
__device__ __forceinline__ uint32_t smem_u32(const void* p) {
    uint32_t a;
    asm("{ .reg .u64 t; cvta.to.shared.u64 t, %1; cvt.u32.u64 %0, t; }" : "=r"(a) : "l"(p));
    return a;
}
__device__ __forceinline__ void ldsm4(uint32_t r[4], uint32_t addr) {
    asm volatile("ldmatrix.sync.aligned.m8n8.x4.shared.b16 {%0,%1,%2,%3}, [%4];"
        : "=r"(r[0]), "=r"(r[1]), "=r"(r[2]), "=r"(r[3]) : "r"(addr));
}
__device__ __forceinline__ void ldsm4t(uint32_t r[4], uint32_t addr) {
    asm volatile("ldmatrix.sync.aligned.m8n8.x4.trans.shared.b16 {%0,%1,%2,%3}, [%4];"
        : "=r"(r[0]), "=r"(r[1]), "=r"(r[2]), "=r"(r[3]) : "r"(addr));
}
__device__ __forceinline__ void mma_f16(float c[4], const uint32_t a[4], uint32_t b0, uint32_t b1) {
    asm volatile(
        "mma.sync.aligned.m16n8k16.row.col.f32.f16.f16.f32 "
        "{%0,%1,%2,%3}, {%4,%5,%6,%7}, {%8,%9}, {%0,%1,%2,%3};\n"
        : "+f"(c[0]), "+f"(c[1]), "+f"(c[2]), "+f"(c[3])
        : "r"(a[0]), "r"(a[1]), "r"(a[2]), "r"(a[3]), "r"(b0), "r"(b1));
}
__device__ __forceinline__ uint32_t pack_h2(__half a, __half b) {
    __half2 h = __halves2half2(a, b);
    return *(uint32_t*)&h;
}
__device__ __forceinline__ float silu_f(float g) { return g / (1.f + __expf(-g)); }

// ============================ router ============================
__global__ void router_kernel(const float* __restrict__ x,
                              const float* __restrict__ rw,
                              const float* __restrict__ seg)
{
    int t = blockIdx.x;
    int tid = threadIdx.x;              // 64 threads
    __shared__ float xs[HH];
    __shared__ float lg[EE];
    __shared__ float red[64];
    const float* xr = x + (size_t)t*HH;
    for (int i = tid; i < HH; i += 64) xs[i] = xr[i];
    __syncthreads();
    if (tid < EE) {
        float a=0.f,b=0.f,c=0.f,d=0.f;
        for (int k = 0; k < HH; k += 4) {
            a = fmaf(xs[k+0], rw[(size_t)(k+0)*EE + tid], a);
            b = fmaf(xs[k+1], rw[(size_t)(k+1)*EE + tid], b);
            c = fmaf(xs[k+2], rw[(size_t)(k+2)*EE + tid], c);
            d = fmaf(xs[k+3], rw[(size_t)(k+3)*EE + tid], d);
        }
        lg[tid] = (a+b)+(c+d);
    }
    float p = 0.f;
    for (int k = tid; k < HH; k += 64) p = fmaf(xs[k], seg[k], p);
    red[tid] = p;
    __syncthreads();
    if (tid == 0) {
        float m = lg[0];
        for (int e = 1; e < EE; e++) m = fmaxf(m, lg[e]);
        float s = 0.f;
        for (int e = 0; e < EE; e++) { float v = __expf(lg[e]-m); lg[e] = v; s += v; }
        float inv = 1.f/s;
        for (int e = 0; e < EE; e++) lg[e] *= inv;
        for (int j = 0; j < TK; j++) {
            int bi = 0; float bv = lg[0];
            for (int e = 1; e < EE; e++) { if (lg[e] > bv) { bv = lg[e]; bi = e; } }
            g_topidx[t*TK+j] = bi;
            g_topw[t*TK+j]  = bv;
            lg[bi] = -1.f;
        }
        float ss = 0.f;
        for (int i = 0; i < 64; i++) ss += red[i];
        g_sig[t] = 1.f/(1.f + __expf(-ss));
    }
}

__global__ void build1_kernel()
{
    __shared__ int cnt[EE];
    int tid = threadIdx.x;              // 256
    if (tid < EE) cnt[tid] = 0;
    __syncthreads();
    for (int p = tid; p < NP; p += 256) atomicAdd(&cnt[g_topidx[p]], 1);
    __syncthreads();
    if (tid == 0) {
        int s = 0;
        for (int e = 0; e < EE; e++) { g_off[e] = s; s += cnt[e]; }
        g_off[EE] = s;
    }
}

__global__ void build2_kernel()
{
    __shared__ int sidx[NP];            // 32 KB
    int tid = threadIdx.x;              // 256, grid 32
    for (int i = tid; i < NP; i += 256) sidx[i] = g_topidx[i];
    __syncthreads();
    int p = blockIdx.x*256 + tid;
    int e = sidx[p];
    int r = 0;
    for (int q = 0; q < p; q++) r += (sidx[q] == e);
    int pos = g_off[e] + r;
    g_tok[pos] = p >> 2;
    g_pos[p]   = pos;
}

// ============================ HMMA GEMM ============================
// CTA tile 128x256, BK=32, 8 warps, warp tile 64x64 (grid 2x4).
// A: fp16x2 split (hi/lo); B: single fp16.
// Stage: Ahi [128][40]h (10240B) | Alo (10240B) | B [32][264]h (16896B)
#define ALO_OF 10240
#define B_OF   20480
#define STG    37376
#define SMEM_BYTES (2*STG)
#define BPITCH 528   // bytes per B k-row (264 halves)

// convert 8 floats -> 1 uint4 of fp16
__device__ __forceinline__ uint4 cvt8(const float4& x, const float4& y) {
    uint4 o;
    o.x = pack_h2(__float2half_rn(x.x), __float2half_rn(x.y));
    o.y = pack_h2(__float2half_rn(x.z), __float2half_rn(x.w));
    o.z = pack_h2(__float2half_rn(y.x), __float2half_rn(y.y));
    o.w = pack_h2(__float2half_rn(y.z), __float2half_rn(y.w));
    return o;
}
// residual of 8 floats vs their fp16 -> 1 uint4 of fp16
__device__ __forceinline__ uint4 cvt8lo(const float4& x, const float4& y) {
    uint4 o;
    o.x = pack_h2(__float2half_rn(x.x - __half2float(__float2half_rn(x.x))),
                  __float2half_rn(x.y - __half2float(__float2half_rn(x.y))));
    o.y = pack_h2(__float2half_rn(x.z - __half2float(__float2half_rn(x.z))),
                  __float2half_rn(x.w - __half2float(__float2half_rn(x.w))));
    o.z = pack_h2(__float2half_rn(y.x - __half2float(__float2half_rn(y.x))),
                  __float2half_rn(y.y - __half2float(__float2half_rn(y.y))));
    o.w = pack_h2(__float2half_rn(y.z - __half2float(__float2half_rn(y.z))),
                  __float2half_rn(y.w - __half2float(__float2half_rn(y.w))));
    return o;
}

// store one staged slab from regs (A: 4 float4 per thread; B: 8 float4 per thread)
__device__ __forceinline__ void store_stage(char* buf, const float4 pa[4], const float4 pb[8],
                                            int ar, int ah, int bk, int bn0)
{
    char* pah = buf + ar*80 + ah*2;
    *(uint4*)(pah)      = cvt8(pa[0], pa[1]);
    *(uint4*)(pah + 16) = cvt8(pa[2], pa[3]);
    char* pal = buf + ALO_OF + ar*80 + ah*2;
    *(uint4*)(pal)      = cvt8lo(pa[0], pa[1]);
    *(uint4*)(pal + 16) = cvt8lo(pa[2], pa[3]);
    char* pb0 = buf + B_OF + bk*BPITCH + bn0*2;
    *(uint4*)(pb0)       = cvt8(pb[0], pb[1]);
    *(uint4*)(pb0 + 16)  = cvt8(pb[2], pb[3]);
    *(uint4*)(pb0 + 256) = cvt8(pb[4], pb[5]);   // second chunk at +128 cols
    *(uint4*)(pb0 + 272) = cvt8(pb[6], pb[7]);
}

// MOE=false: MODE0 ybuf=x@shg | MODE1 ybuf=silu(ybuf)*(x@shu) | MODE2 out=sig*(ybuf@shd)
// MOE=true : MODE0 hbuf=x[tok]@wg[e] | MODE1 hbuf=silu(hbuf)*(x[tok]@wu[e]) | MODE2 pbuf=hbuf@wd[e]
template<int MODE, bool MOE>
__global__ void __launch_bounds__(256,1) gemm_hmma(const float* __restrict__ Aex,
                                                   const float* __restrict__ Bw,
                                                   float* __restrict__ Cex)
{
    constexpr int K = MOE ? ((MODE==2) ? FF : HH) : ((MODE==2) ? SS : HH);
    constexpr int N = MOE ? ((MODE==2) ? HH : FF) : ((MODE==2) ? HH : SS);
    constexpr int NSLAB = K/32;

    extern __shared__ __align__(16) char dsm[];
    const uint32_t sb = smem_u32(dsm);

    const int tid = threadIdx.x, lane = tid & 31, w = tid >> 5;
    const int wm = (w & 1)*64, wn = (w >> 1)*64;

    int e = 0, off = 0, cnt = TT;
    if (MOE) { e = blockIdx.z; off = g_off[e]; cnt = g_off[e+1] - off; }
    const int mb = blockIdx.y*128;
    if (MOE && mb >= cnt) return;
    const int nb = blockIdx.x*256;
    const float* Bp = MOE ? Bw + (size_t)e*K*N : Bw;
    const float* Abase = (!MOE && MODE==2) ? (const float*)g_ybuf
                       : ( MOE && MODE==2) ? (const float*)g_hbuf
                       : Aex;

    // fill mappings
    const int ar = tid >> 1, ah = (tid & 1)*16;
    const float* aptr;
    {
        int rl = mb + ar;
        if (MOE) {
            int rc = (rl < cnt) ? rl : (cnt - 1);
            if (MODE < 2) aptr = Abase + (size_t)g_tok[off + rc]*HH + ah;
            else          aptr = Abase + (size_t)(off + rc)*FF + ah;
        } else {
            aptr = Abase + (size_t)rl*K + ah;
        }
    }
    const int bk = tid >> 3, bn0 = (tid & 7)*16;
    int c0 = nb + bn0;       if (c0 > N-16) c0 = N-16;
    int c1 = nb + bn0 + 128; if (c1 > N-16) c1 = N-16;
    const float* bptr0 = Bp + (size_t)bk*N + c0;
    const float* bptr1 = Bp + (size_t)bk*N + c1;

    // fragment addresses within a stage
    const int lr = lane & 15, lc = lane >> 4;
    uint32_t aoffh[4];
    #pragma unroll
    for (int mi = 0; mi < 4; mi++)
        aoffh[mi] = (uint32_t)(((wm + mi*16 + lr)*40 + lc*8)*2);
    uint32_t boff[4];
    #pragma unroll
    for (int np = 0; np < 4; np++)
        boff[np] = (uint32_t)((lr*264 + wn + np*16 + lc*8)*2) + B_OF;

    float acc[4][8][4] = {};

    // prologue: load + stage slab 0
    {
        float4 pa[4], pb[8];
        #pragma unroll
        for (int i = 0; i < 4; i++) pa[i] = *(const float4*)(aptr + i*4);
        #pragma unroll
        for (int i = 0; i < 4; i++) pb[i]   = *(const float4*)(bptr0 + i*4);
        #pragma unroll
        for (int i = 0; i < 4; i++) pb[4+i] = *(const float4*)(bptr1 + i*4);
        store_stage(dsm, pa, pb, ar, ah, bk, bn0);
    }
    __syncthreads();

    for (int s = 0; s < NSLAB; s++) {
        const uint32_t sbb = sb + (uint32_t)((s & 1)*STG);
        const bool more = (s + 1 < NSLAB);
        float4 pa[4], pb[8];
        if (more) {
            const float* ap  = aptr + (s+1)*32;
            const float* bp0 = bptr0 + (size_t)(s+1)*32*N;
            const float* bp1 = bptr1 + (size_t)(s+1)*32*N;
            #pragma unroll
            for (int i = 0; i < 4; i++) pa[i] = *(const float4*)(ap + i*4);
            #pragma unroll
            for (int i = 0; i < 4; i++) pb[i]   = *(const float4*)(bp0 + i*4);
            #pragma unroll
            for (int i = 0; i < 4; i++) pb[4+i] = *(const float4*)(bp1 + i*4);
        }

        // ---- ks = 0 (LDG latency hidden under these MMAs) ----
        {
            uint32_t ahf[4][4], alf[4][4];
            #pragma unroll
            for (int mi = 0; mi < 4; mi++) {
                ldsm4(ahf[mi], sbb + aoffh[mi]);
                ldsm4(alf[mi], sbb + aoffh[mi] + ALO_OF);
            }
            #pragma unroll
            for (int np = 0; np < 4; np++) {
                uint32_t bb[4];
                ldsm4t(bb, sbb + boff[np]);
                #pragma unroll
                for (int mi = 0; mi < 4; mi++) {
                    mma_f16(acc[mi][2*np],   ahf[mi], bb[0], bb[1]);
                    mma_f16(acc[mi][2*np],   alf[mi], bb[0], bb[1]);
                    mma_f16(acc[mi][2*np+1], ahf[mi], bb[2], bb[3]);
                    mma_f16(acc[mi][2*np+1], alf[mi], bb[2], bb[3]);
                }
            }
        }
        // stage next slab (frees prefetch regs before ks=1)
        if (more)
            store_stage(dsm + ((s+1) & 1)*STG, pa, pb, ar, ah, bk, bn0);
        // ---- ks = 1 ----
        {
            uint32_t ahf[4][4], alf[4][4];
            #pragma unroll
            for (int mi = 0; mi < 4; mi++) {
                ldsm4(ahf[mi], sbb + aoffh[mi] + 32);
                ldsm4(alf[mi], sbb + aoffh[mi] + ALO_OF + 32);
            }
            #pragma unroll
            for (int np = 0; np < 4; np++) {
                uint32_t bb[4];
                ldsm4t(bb, sbb + boff[np] + 16*BPITCH);
                #pragma unroll
                for (int mi = 0; mi < 4; mi++) {
                    mma_f16(acc[mi][2*np],   ahf[mi], bb[0], bb[1]);
                    mma_f16(acc[mi][2*np],   alf[mi], bb[0], bb[1]);
                    mma_f16(acc[mi][2*np+1], ahf[mi], bb[2], bb[3]);
                    mma_f16(acc[mi][2*np+1], alf[mi], bb[2], bb[3]);
                }
            }
        }
        __syncthreads();
    }

    // ---- epilogue ----
    #pragma unroll
    for (int mi = 0; mi < 4; mi++) {
        const int rl0 = mb + wm + mi*16 + (lane >> 2);
        const int rl1 = rl0 + 8;
        const bool v0 = MOE ? (rl0 < cnt) : true;
        const bool v1 = MOE ? (rl1 < cnt) : true;
        #pragma unroll
        for (int nt = 0; nt < 8; nt++) {
            const int col = nb + wn + nt*8 + (lane & 3)*2;
            if (MOE && col >= N) continue;
            const float* c = acc[mi][nt];
            if (!MOE) {
                if (MODE == 0) {
                    *(float2*)&g_ybuf[(size_t)rl0*SS + col] = make_float2(c[0], c[1]);
                    *(float2*)&g_ybuf[(size_t)rl1*SS + col] = make_float2(c[2], c[3]);
                } else if (MODE == 1) {
                    float2 g0 = *(float2*)&g_ybuf[(size_t)rl0*SS + col];
                    float2 g1 = *(float2*)&g_ybuf[(size_t)rl1*SS + col];
                    *(float2*)&g_ybuf[(size_t)rl0*SS + col] =
                        make_float2(silu_f(g0.x)*c[0], silu_f(g0.y)*c[1]);
                    *(float2*)&g_ybuf[(size_t)rl1*SS + col] =
                        make_float2(silu_f(g1.x)*c[2], silu_f(g1.y)*c[3]);
                } else {
                    float s0 = g_sig[rl0], s1 = g_sig[rl1];
                    *(float2*)&Cex[(size_t)rl0*HH + col] = make_float2(s0*c[0], s0*c[1]);
                    *(float2*)&Cex[(size_t)rl1*HH + col] = make_float2(s1*c[2], s1*c[3]);
                }
            } else {
                if (MODE == 0) {
                    if (v0) *(float2*)&g_hbuf[(size_t)(off+rl0)*FF + col] = make_float2(c[0], c[1]);
                    if (v1) *(float2*)&g_hbuf[(size_t)(off+rl1)*FF + col] = make_float2(c[2], c[3]);
                } else if (MODE == 1) {
                    if (v0) {
                        float2 g = *(float2*)&g_hbuf[(size_t)(off+rl0)*FF + col];
                        *(float2*)&g_hbuf[(size_t)(off+rl0)*FF + col] =
                            make_float2(silu_f(g.x)*c[0], silu_f(g.y)*c[1]);
                    }
                    if (v1) {
                        float2 g = *(float2*)&g_hbuf[(size_t)(off+rl1)*FF + col];
                        *(float2*)&g_hbuf[(size_t)(off+rl1)*FF + col] =
                            make_float2(silu_f(g.x)*c[2], silu_f(g.y)*c[3]);
                    }
                } else {
                    if (v0) *(float2*)&g_pbuf[(size_t)(off+rl0)*HH + col] = make_float2(c[0], c[1]);
                    if (v1) *(float2*)&g_pbuf[(size_t)(off+rl1)*HH + col] = make_float2(c[2], c[3]);
                }
            }
        }
    }
}

// ============================ combine ============================
__global__ void combine_kernel(float* __restrict__ out)
{
    int t = blockIdx.x, tid = threadIdx.x;
    int p0 = g_pos[t*4+0], p1 = g_pos[t*4+1], p2 = g_pos[t*4+2], p3 = g_pos[t*4+3];
    float w0 = g_topw[t*4+0], w1 = g_topw[t*4+1], w2 = g_topw[t*4+2], w3 = g_topw[t*4+3];
    const float* r0 = g_pbuf + (size_t)p0*HH;
    const float* r1 = g_pbuf + (size_t)p1*HH;
    const float* r2 = g_pbuf + (size_t)p2*HH;
    const float* r3 = g_pbuf + (size_t)p3*HH;
    for (int c = tid; c < HH; c += 256) {
        float v = out[(size_t)t*HH + c];
        v = fmaf(w0, r0[c], v);
        v = fmaf(w1, r1[c], v);
        v = fmaf(w2, r2[c], v);
        v = fmaf(w3, r3[c], v);
        out[(size_t)t*HH + c] = v;
    }
}

// ============================ launch ============================
extern "C" void kernel_launch(void* const* d_in, const int* in_sizes, int n_in,
                              void* d_out, int out_size)
{
    const float* x   = (const float*)d_in[0];
    const float* rw  = (const float*)d_in[1];
    const float* wg  = (const float*)d_in[2];
    const float* wu  = (const float*)d_in[3];
    const float* wd  = (const float*)d_in[4];
    const float* shg = (const float*)d_in[5];
    const float* shu = (const float*)d_in[6];
    const float* shd = (const float*)d_in[7];
    const float* seg = (const float*)d_in[8];
    float* out = (float*)d_out;
    (void)in_sizes; (void)n_in; (void)out_size;

    cudaFuncSetAttribute(gemm_hmma<0,false>, cudaFuncAttributeMaxDynamicSharedMemorySize, SMEM_BYTES);
    cudaFuncSetAttribute(gemm_hmma<1,false>, cudaFuncAttributeMaxDynamicSharedMemorySize, SMEM_BYTES);
    cudaFuncSetAttribute(gemm_hmma<2,false>, cudaFuncAttributeMaxDynamicSharedMemorySize, SMEM_BYTES);
    cudaFuncSetAttribute(gemm_hmma<0,true>,  cudaFuncAttributeMaxDynamicSharedMemorySize, SMEM_BYTES);
    cudaFuncSetAttribute(gemm_hmma<1,true>,  cudaFuncAttributeMaxDynamicSharedMemorySize, SMEM_BYTES);
    cudaFuncSetAttribute(gemm_hmma<2,true>,  cudaFuncAttributeMaxDynamicSharedMemorySize, SMEM_BYTES);

    router_kernel<<<TT, 64>>>(x, rw, seg);
    build1_kernel<<<1, 256>>>();
    build2_kernel<<<32, 256>>>();

    // shared expert: N tiles of 256
    gemm_hmma<0,false><<<dim3(SS/256, TT/128), 256, SMEM_BYTES>>>(x, shg, nullptr);
    gemm_hmma<1,false><<<dim3(SS/256, TT/128), 256, SMEM_BYTES>>>(x, shu, nullptr);
    gemm_hmma<2,false><<<dim3(HH/256, TT/128), 256, SMEM_BYTES>>>(nullptr, shd, out);

    // MoE experts (per-expert z grid, padded 128-row M tiles)
    gemm_hmma<0,true><<<dim3((FF+255)/256, TT/128, EE), 256, SMEM_BYTES>>>(x, wg, nullptr);
    gemm_hmma<1,true><<<dim3((FF+255)/256, TT/128, EE), 256, SMEM_BYTES>>>(x, wu, nullptr);
    gemm_hmma<2,true><<<dim3(HH/256, TT/128, EE), 256, SMEM_BYTES>>>(nullptr, wd, nullptr);

    combine_kernel<<<TT, 256>>>(out);
}

// round 8
// speedup vs baseline: 1.7066x; 1.6415x over previous
#include <cuda_runtime.h>
#include <cuda_fp16.h>
#include <stdint.h>
#include <math.h>

#define TT 2048     // tokens
#define HH 2048     // hidden
#define FF 1408     // moe intermediate
#define EE 60       // experts
#define TK 4        // top-k
#define SS 5632     // shared intermediate
#define NP (TT*TK)  // routed pairs

// ---- fp16 operand buffers (converted once per call) ----
__device__ __align__(16) __half g_wgh[(size_t)EE*HH*FF];
__device__ __align__(16) __half g_wuh[(size_t)EE*HH*FF];
__device__ __align__(16) __half g_wdh[(size_t)EE*FF*HH];
__device__ __align__(16) __half g_shgh[(size_t)HH*SS];
__device__ __align__(16) __half g_shuh[(size_t)HH*SS];
__device__ __align__(16) __half g_shdh[(size_t)SS*HH];
__device__ __align__(16) __half g_xh[(size_t)TT*HH];
// ---- intermediates ----
__device__ __align__(16) __half g_ybuf16[(size_t)TT*SS];
__device__ __align__(16) __half g_hbuf16[(size_t)NP*FF];
__device__ float g_pbuf[(size_t)NP*HH];
// ---- routing ----
__device__ float g_topw[NP];
__device__ int   g_topidx[NP];
__device__ float g_sig[TT];
__device__ int   g_off[EE+1];
__device__ int   g_tok[NP];
__device__ int   g_pos[NP];

// ============================ helpers ============================
__device__ __forceinline__ uint32_t smem_u32(const void* p) {
    uint32_t a;
    asm("{ .reg .u64 t; cvta.to.shared.u64 t, %1; cvt.u32.u64 %0, t; }" : "=r"(a) : "l"(p));
    return a;
}
__device__ __forceinline__ void ldsm4(uint32_t r[4], uint32_t addr) {
    asm volatile("ldmatrix.sync.aligned.m8n8.x4.shared.b16 {%0,%1,%2,%3}, [%4];"
        : "=r"(r[0]), "=r"(r[1]), "=r"(r[2]), "=r"(r[3]) : "r"(addr));
}
__device__ __forceinline__ void ldsm4t(uint32_t r[4], uint32_t addr) {
    asm volatile("ldmatrix.sync.aligned.m8n8.x4.trans.shared.b16 {%0,%1,%2,%3}, [%4];"
        : "=r"(r[0]), "=r"(r[1]), "=r"(r[2]), "=r"(r[3]) : "r"(addr));
}
__device__ __forceinline__ void mma_f16(float c[4], const uint32_t a[4], uint32_t b0, uint32_t b1) {
    asm volatile(
        "mma.sync.aligned.m16n8k16.row.col.f32.f16.f16.f32 "
        "{%0,%1,%2,%3}, {%4,%5,%6,%7}, {%8,%9}, {%0,%1,%2,%3};\n"
        : "+f"(c[0]), "+f"(c[1]), "+f"(c[2]), "+f"(c[3])
        : "r"(a[0]), "r"(a[1]), "r"(a[2]), "r"(a[3]), "r"(b0), "r"(b1));
}
__device__ __forceinline__ uint32_t pack_h2(__half a, __half b) {
    __half2 h = __halves2half2(a, b);
    return *(uint32_t*)&h;
}
__device__ __forceinline__ float silu_f(float g) { return g / (1.f + __expf(-g)); }

#define CP16(d, s)  asm volatile("cp.async.cg.shared.global [%0], [%1], 16;" :: "r"(d), "l"(s))
#define CPCOMMIT()  asm volatile("cp.async.commit_group;" ::: "memory")
#define CPWAIT2()   asm volatile("cp.async.wait_group 2;" ::: "memory")

// ============================ fp32 -> fp16 conversion ============================
// which: 0 wg, 1 wu, 2 wd, 3 shg, 4 shu, 5 shd, 6 x
__global__ void cvt_kernel(const float* __restrict__ src, int which, int n8)
{
    int i = blockIdx.x*256 + threadIdx.x;
    if (i >= n8) return;
    __half* dst = (which==0) ? g_wgh : (which==1) ? g_wuh : (which==2) ? g_wdh
                : (which==3) ? g_shgh : (which==4) ? g_shuh : (which==5) ? g_shdh : g_xh;
    const float4* s4 = (const float4*)src;
    float4 a = s4[2*i], b = s4[2*i+1];
    uint4 o;
    o.x = pack_h2(__float2half_rn(a.x), __float2half_rn(a.y));
    o.y = pack_h2(__float2half_rn(a.z), __float2half_rn(a.w));
    o.z = pack_h2(__float2half_rn(b.x), __float2half_rn(b.y));
    o.w = pack_h2(__float2half_rn(b.z), __float2half_rn(b.w));
    ((uint4*)dst)[i] = o;
}

// ============================ router ============================
__global__ void router_kernel(const float* __restrict__ x,
                              const float* __restrict__ rw,
                              const float* __restrict__ seg)
{
    int t = blockIdx.x;
    int tid = threadIdx.x;              // 64 threads
    __shared__ float xs[HH];
    __shared__ float lg[EE];
    __shared__ float red[64];
    const float* xr = x + (size_t)t*HH;
    for (int i = tid; i < HH; i += 64) xs[i] = xr[i];
    __syncthreads();
    if (tid < EE) {
        float a=0.f,b=0.f,c=0.f,d=0.f;
        for (int k = 0; k < HH; k += 4) {
            a = fmaf(xs[k+0], rw[(size_t)(k+0)*EE + tid], a);
            b = fmaf(xs[k+1], rw[(size_t)(k+1)*EE + tid], b);
            c = fmaf(xs[k+2], rw[(size_t)(k+2)*EE + tid], c);
            d = fmaf(xs[k+3], rw[(size_t)(k+3)*EE + tid], d);
        }
        lg[tid] = (a+b)+(c+d);
    }
    float p = 0.f;
    for (int k = tid; k < HH; k += 64) p = fmaf(xs[k], seg[k], p);
    red[tid] = p;
    __syncthreads();
    if (tid == 0) {
        float m = lg[0];
        for (int e = 1; e < EE; e++) m = fmaxf(m, lg[e]);
        float s = 0.f;
        for (int e = 0; e < EE; e++) { float v = __expf(lg[e]-m); lg[e] = v; s += v; }
        float inv = 1.f/s;
        for (int e = 0; e < EE; e++) lg[e] *= inv;
        for (int j = 0; j < TK; j++) {
            int bi = 0; float bv = lg[0];
            for (int e = 1; e < EE; e++) { if (lg[e] > bv) { bv = lg[e]; bi = e; } }
            g_topidx[t*TK+j] = bi;
            g_topw[t*TK+j]  = bv;
            lg[bi] = -1.f;
        }
        float ss = 0.f;
        for (int i = 0; i < 64; i++) ss += red[i];
        g_sig[t] = 1.f/(1.f + __expf(-ss));
    }
}

__global__ void build1_kernel()
{
    __shared__ int cnt[EE];
    int tid = threadIdx.x;              // 256
    if (tid < EE) cnt[tid] = 0;
    __syncthreads();
    for (int p = tid; p < NP; p += 256) atomicAdd(&cnt[g_topidx[p]], 1);
    __syncthreads();
    if (tid == 0) {
        int s = 0;
        for (int e = 0; e < EE; e++) { g_off[e] = s; s += cnt[e]; }
        g_off[EE] = s;
    }
}

__global__ void build2_kernel()
{
    __shared__ int sidx[NP];            // 32 KB
    int tid = threadIdx.x;              // 256, grid 32
    for (int i = tid; i < NP; i += 256) sidx[i] = g_topidx[i];
    __syncthreads();
    int p = blockIdx.x*256 + tid;
    int e = sidx[p];
    int r = 0;
    for (int q = 0; q < p; q++) r += (sidx[q] == e);
    int pos = g_off[e] + r;
    g_tok[pos] = p >> 2;
    g_pos[p]   = pos;
}

// ============================ cp.async HMMA GEMM ============================
// CTA 128x128, BK=32, 8 warps (warp 32x64), fp16 A and B, 4-stage cp.async.
// Stage: A [128 rows x 80B pitch] (10240B) | B [32 rows x 272B pitch] (8704B)
#define STAGEB 18944
#define B_OF   10240
#define GSMEM  (4*STAGEB)

// MOE=false: MODE0 y16=x@shg | MODE1 y16=silu(y16)*(x@shu) | MODE2 out=sig*(y16@shd)
// MOE=true : MODE0 h16=x[tok]@wg[e] | MODE1 h16=silu(h16)*(x[tok]@wu[e]) | MODE2 pbuf=h16@wd[e]
template<int MODE, bool MOE>
__global__ void __launch_bounds__(256,2) gemm_cp(float* __restrict__ Cex)
{
    constexpr int K = MOE ? ((MODE==2) ? FF : HH) : ((MODE==2) ? SS : HH);
    constexpr int N = MOE ? ((MODE==2) ? HH : FF) : ((MODE==2) ? HH : SS);
    constexpr int NSLAB = K/32;

    extern __shared__ __align__(16) char dsm[];
    const uint32_t sb = smem_u32(dsm);

    const int tid = threadIdx.x, lane = tid & 31, w = tid >> 5;
    const int wm = (w & 3)*32, wn = (w >> 2)*64;

    int e = 0, off = 0, cnt = TT;
    if (MOE) { e = blockIdx.z; off = g_off[e]; cnt = g_off[e+1] - off; }
    const int mb = blockIdx.y*128;
    if (MOE && mb >= cnt) return;
    const int nb = blockIdx.x*128;

    const __half* Bh = MOE ? ((MODE==0) ? g_wgh : (MODE==1) ? g_wuh : g_wdh)
                           : ((MODE==0) ? g_shgh : (MODE==1) ? g_shuh : g_shdh);
    const __half* Bp = MOE ? Bh + (size_t)e*K*N : Bh;

    // ---- A fill pointers (2 rows per thread, 8 halves each) ----
    const int aseg = tid & 3, ar0 = tid >> 2, ar1 = (tid >> 2) + 64;
    const __half *pa0, *pa1;
    if (MOE) {
        int rc0 = (mb+ar0 < cnt) ? (mb+ar0) : (cnt-1);
        int rc1 = (mb+ar1 < cnt) ? (mb+ar1) : (cnt-1);
        if (MODE < 2) {
            pa0 = g_xh + (size_t)g_tok[off+rc0]*HH + aseg*8;
            pa1 = g_xh + (size_t)g_tok[off+rc1]*HH + aseg*8;
        } else {
            pa0 = g_hbuf16 + (size_t)(off+rc0)*FF + aseg*8;
            pa1 = g_hbuf16 + (size_t)(off+rc1)*FF + aseg*8;
        }
    } else {
        const __half* Ah = (MODE==2) ? g_ybuf16 : g_xh;
        pa0 = Ah + (size_t)(mb+ar0)*K + aseg*8;
        pa1 = Ah + (size_t)(mb+ar1)*K + aseg*8;
    }
    const uint32_t dA0 = (uint32_t)(ar0*80 + aseg*16);
    const uint32_t dA1 = (uint32_t)(ar1*80 + aseg*16);

    // ---- B fill pointers (2 rows per thread, 8 halves each) ----
    const int bseg = tid & 15, br0 = tid >> 4, br1 = (tid >> 4) + 16;
    const __half* pb0 = Bp + (size_t)br0*N + nb + bseg*8;
    const __half* pb1 = Bp + (size_t)br1*N + nb + bseg*8;
    const uint32_t dB0 = (uint32_t)(B_OF + br0*272 + bseg*16);
    const uint32_t dB1 = (uint32_t)(B_OF + br1*272 + bseg*16);

    // ---- fragment addresses ----
    const int lr = lane & 15, lc = lane >> 4;
    const uint32_t aoff0 = (uint32_t)((wm + lr)*80 + lc*16);
    const uint32_t aoff1 = aoff0 + 16*80;
    uint32_t boff[4];
    #pragma unroll
    for (int np = 0; np < 4; np++)
        boff[np] = (uint32_t)(B_OF + lr*272 + (wn + np*16 + lc*8)*2);

    float acc[2][8][4] = {};

    // ---- prologue: fill stages 0..2 ----
    #pragma unroll
    for (int s = 0; s < 3; s++) {
        uint32_t base = sb + s*STAGEB;
        CP16(base + dA0, pa0 + s*32);
        CP16(base + dA1, pa1 + s*32);
        CP16(base + dB0, pb0 + (size_t)s*32*N);
        CP16(base + dB1, pb1 + (size_t)s*32*N);
        CPCOMMIT();
    }

    for (int s = 0; s < NSLAB; s++) {
        CPWAIT2();
        __syncthreads();
        if (s + 3 < NSLAB) {
            uint32_t base = sb + ((s+3) & 3)*STAGEB;
            CP16(base + dA0, pa0 + (s+3)*32);
            CP16(base + dA1, pa1 + (s+3)*32);
            CP16(base + dB0, pb0 + (size_t)(s+3)*32*N);
            CP16(base + dB1, pb1 + (size_t)(s+3)*32*N);
        }
        CPCOMMIT();   // unconditional: keeps group count aligned in tail
        const uint32_t sbb = sb + (uint32_t)((s & 3)*STAGEB);
        #pragma unroll
        for (int ks = 0; ks < 2; ks++) {
            uint32_t a0[4], a1[4];
            ldsm4(a0, sbb + aoff0 + ks*32);
            ldsm4(a1, sbb + aoff1 + ks*32);
            #pragma unroll
            for (int np = 0; np < 4; np++) {
                uint32_t bb[4];
                ldsm4t(bb, sbb + boff[np] + ks*16*272);
                mma_f16(acc[0][2*np],   a0, bb[0], bb[1]);
                mma_f16(acc[0][2*np+1], a0, bb[2], bb[3]);
                mma_f16(acc[1][2*np],   a1, bb[0], bb[1]);
                mma_f16(acc[1][2*np+1], a1, bb[2], bb[3]);
            }
        }
    }

    // ---- epilogue ----
    #pragma unroll
    for (int mt = 0; mt < 2; mt++) {
        const int rl0 = mb + wm + mt*16 + (lane >> 2);
        const int rl1 = rl0 + 8;
        const bool v0 = MOE ? (rl0 < cnt) : true;
        const bool v1 = MOE ? (rl1 < cnt) : true;
        #pragma unroll
        for (int nt = 0; nt < 8; nt++) {
            const int col = nb + wn + nt*8 + (lane & 3)*2;
            const float* c = acc[mt][nt];
            if (!MOE) {
                if (MODE == 0) {
                    *(__half2*)&g_ybuf16[(size_t)rl0*SS + col] = __floats2half2_rn(c[0], c[1]);
                    *(__half2*)&g_ybuf16[(size_t)rl1*SS + col] = __floats2half2_rn(c[2], c[3]);
                } else if (MODE == 1) {
                    __half2 ga = *(__half2*)&g_ybuf16[(size_t)rl0*SS + col];
                    __half2 gb = *(__half2*)&g_ybuf16[(size_t)rl1*SS + col];
                    *(__half2*)&g_ybuf16[(size_t)rl0*SS + col] =
                        __floats2half2_rn(silu_f(__half2float(ga.x))*c[0],
                                          silu_f(__half2float(ga.y))*c[1]);
                    *(__half2*)&g_ybuf16[(size_t)rl1*SS + col] =
                        __floats2half2_rn(silu_f(__half2float(gb.x))*c[2],
                                          silu_f(__half2float(gb.y))*c[3]);
                } else {
                    float s0 = g_sig[rl0], s1 = g_sig[rl1];
                    *(float2*)&Cex[(size_t)rl0*HH + col] = make_float2(s0*c[0], s0*c[1]);
                    *(float2*)&Cex[(size_t)rl1*HH + col] = make_float2(s1*c[2], s1*c[3]);
                }
            } else {
                if (MODE == 0) {
                    if (v0) *(__half2*)&g_hbuf16[(size_t)(off+rl0)*FF + col] = __floats2half2_rn(c[0], c[1]);
                    if (v1) *(__half2*)&g_hbuf16[(size_t)(off+rl1)*FF + col] = __floats2half2_rn(c[2], c[3]);
                } else if (MODE == 1) {
                    if (v0) {
                        __half2 g = *(__half2*)&g_hbuf16[(size_t)(off+rl0)*FF + col];
                        *(__half2*)&g_hbuf16[(size_t)(off+rl0)*FF + col] =
                            __floats2half2_rn(silu_f(__half2float(g.x))*c[0],
                                              silu_f(__half2float(g.y))*c[1]);
                    }
                    if (v1) {
                        __half2 g = *(__half2*)&g_hbuf16[(size_t)(off+rl1)*FF + col];
                        *(__half2*)&g_hbuf16[(size_t)(off+rl1)*FF + col] =
                            __floats2half2_rn(silu_f(__half2float(g.x))*c[2],
                                              silu_f(__half2float(g.y))*c[3]);
                    }
                } else {
                    if (v0) *(float2*)&g_pbuf[(size_t)(off+rl0)*HH + col] = make_float2(c[0], c[1]);
                    if (v1) *(float2*)&g_pbuf[(size_t)(off+rl1)*HH + col] = make_float2(c[2], c[3]);
                }
            }
        }
    }
}

// ============================ combine ============================
__global__ void combine_kernel(float* __restrict__ out)
{
    int t = blockIdx.x, tid = threadIdx.x;
    int p0 = g_pos[t*4+0], p1 = g_pos[t*4+1], p2 = g_pos[t*4+2], p3 = g_pos[t*4+3];
    float w0 = g_topw[t*4+0], w1 = g_topw[t*4+1], w2 = g_topw[t*4+2], w3 = g_topw[t*4+3];
    const float* r0 = g_pbuf + (size_t)p0*HH;
    const float* r1 = g_pbuf + (size_t)p1*HH;
    const float* r2 = g_pbuf + (size_t)p2*HH;
    const float* r3 = g_pbuf + (size_t)p3*HH;
    for (int c = tid; c < HH; c += 256) {
        float v = out[(size_t)t*HH + c];
        v = fmaf(w0, r0[c], v);
        v = fmaf(w1, r1[c], v);
        v = fmaf(w2, r2[c], v);
        v = fmaf(w3, r3[c], v);
        out[(size_t)t*HH + c] = v;
    }
}

// ============================ launch ============================
extern "C" void kernel_launch(void* const* d_in, const int* in_sizes, int n_in,
                              void* d_out, int out_size)
{
    const float* x   = (const float*)d_in[0];
    const float* rw  = (const float*)d_in[1];
    const float* wg  = (const float*)d_in[2];
    const float* wu  = (const float*)d_in[3];
    const float* wd  = (const float*)d_in[4];
    const float* shg = (const float*)d_in[5];
    const float* shu = (const float*)d_in[6];
    const float* shd = (const float*)d_in[7];
    const float* seg = (const float*)d_in[8];
    float* out = (float*)d_out;
    (void)in_sizes; (void)n_in; (void)out_size;

    cudaFuncSetAttribute(gemm_cp<0,false>, cudaFuncAttributeMaxDynamicSharedMemorySize, GSMEM);
    cudaFuncSetAttribute(gemm_cp<1,false>, cudaFuncAttributeMaxDynamicSharedMemorySize, GSMEM);
    cudaFuncSetAttribute(gemm_cp<2,false>, cudaFuncAttributeMaxDynamicSharedMemorySize, GSMEM);
    cudaFuncSetAttribute(gemm_cp<0,true>,  cudaFuncAttributeMaxDynamicSharedMemorySize, GSMEM);
    cudaFuncSetAttribute(gemm_cp<1,true>,  cudaFuncAttributeMaxDynamicSharedMemorySize, GSMEM);
    cudaFuncSetAttribute(gemm_cp<2,true>,  cudaFuncAttributeMaxDynamicSharedMemorySize, GSMEM);

    // ---- fp32 -> fp16 conversions ----
    const int nW  = EE*HH*FF/8;      // 21,626,880
    const int nSH = HH*SS/8;         // 1,441,792
    const int nX  = TT*HH/8;         // 524,288
    cvt_kernel<<<(nW +255)/256, 256>>>(wg,  0, nW);
    cvt_kernel<<<(nW +255)/256, 256>>>(wu,  1, nW);
    cvt_kernel<<<(nW +255)/256, 256>>>(wd,  2, nW);
    cvt_kernel<<<(nSH+255)/256, 256>>>(shg, 3, nSH);
    cvt_kernel<<<(nSH+255)/256, 256>>>(shu, 4, nSH);
    cvt_kernel<<<(nSH+255)/256, 256>>>(shd, 5, nSH);
    cvt_kernel<<<(nX +255)/256, 256>>>(x,   6, nX);

    // ---- routing ----
    router_kernel<<<TT, 64>>>(x, rw, seg);
    build1_kernel<<<1, 256>>>();
    build2_kernel<<<32, 256>>>();

    // ---- shared expert ----
    gemm_cp<0,false><<<dim3(SS/128, TT/128), 256, GSMEM>>>(nullptr);
    gemm_cp<1,false><<<dim3(SS/128, TT/128), 256, GSMEM>>>(nullptr);
    gemm_cp<2,false><<<dim3(HH/128, TT/128), 256, GSMEM>>>(out);

    // ---- MoE experts ----
    gemm_cp<0,true><<<dim3(FF/128, TT/128, EE), 256, GSMEM>>>(nullptr);
    gemm_cp<1,true><<<dim3(FF/128, TT/128, EE), 256, GSMEM>>>(nullptr);
    gemm_cp<2,true><<<dim3(HH/128, TT/128, EE), 256, GSMEM>>>(nullptr);

    combine_kernel<<<TT, 256>>>(out);
}